// round 14
// baseline (speedup 1.0000x reference)
#include <cuda_runtime.h>

#define N_PTS 65536
#define C 64
#define NS 16
#define CSH 8

// scratch for xq | xk | xv  (3 * 16MB)
__device__ __align__(256) float g_qkv[3 * N_PTS * C];

// ---------------------------------------------------------------------------
// Kernel 1: fused q/k/v projection GEMM  (65536x64) @ (64x192)
// block = 256 threads, 64 points per block, K tiled by 32.
// micro-tile per thread: 4 points x 12 output cols (48 FMA per 16 LDS)
// ---------------------------------------------------------------------------
__global__ __launch_bounds__(256) void proj_kernel(
    const float* __restrict__ x,
    const float* __restrict__ Wq, const float* __restrict__ bq,
    const float* __restrict__ Wk, const float* __restrict__ bk,
    const float* __restrict__ Wv, const float* __restrict__ bv)
{
    __shared__ float Ws[32][192];   // 24KB  (k-tile of all 3 weight mats)
    __shared__ float Xs[64][36];    // 9.2KB (pitch 36 -> conflict-free rows)
    __shared__ float bs[192];

    const int tid = threadIdx.x;
    const int pB  = blockIdx.x * 64;

    if (tid < 192)
        bs[tid] = (tid < 64) ? bq[tid] : (tid < 128 ? bk[tid - 64] : bv[tid - 128]);

    const int pg = tid >> 4;    // 0..15 point group (4 points each)
    const int og = tid & 15;    // 0..15 output group (12 cols each)

    float acc[4][12];
    #pragma unroll
    for (int i = 0; i < 4; i++)
        #pragma unroll
        for (int j = 0; j < 12; j++) acc[i][j] = 0.f;

    for (int kt = 0; kt < 2; kt++) {
        __syncthreads();
        // load weight k-tile: rows kt*32..kt*32+31 of [Wq|Wk|Wv]
        for (int idx = tid; idx < 32 * 192; idx += 256) {
            int kk = idx / 192, col = idx % 192;
            int mat = col >> 6, ch = col & 63;
            const float* Wp = (mat == 0) ? Wq : ((mat == 1) ? Wk : Wv);
            Ws[kk][col] = Wp[(kt * 32 + kk) * 64 + ch];
        }
        // load x k-tile
        for (int idx = tid; idx < 64 * 32; idx += 256) {
            int pt = idx >> 5, kk = idx & 31;
            Xs[pt][kk] = x[(pB + pt) * 64 + kt * 32 + kk];
        }
        __syncthreads();

        #pragma unroll 8
        for (int kk = 0; kk < 32; kk++) {
            float xp[4], wv[12];
            #pragma unroll
            for (int i = 0; i < 4; i++) xp[i] = Xs[pg * 4 + i][kk];
            #pragma unroll
            for (int j = 0; j < 12; j++) wv[j] = Ws[kk][og * 12 + j];
            #pragma unroll
            for (int i = 0; i < 4; i++)
                #pragma unroll
                for (int j = 0; j < 12; j++)
                    acc[i][j] = fmaf(xp[i], wv[j], acc[i][j]);
        }
    }

    #pragma unroll
    for (int i = 0; i < 4; i++) {
        int pt = pB + pg * 4 + i;
        #pragma unroll
        for (int j = 0; j < 12; j++) {
            int col = og * 12 + j;
            int mat = col >> 6, ch = col & 63;
            g_qkv[mat * (N_PTS * C) + pt * C + ch] = acc[i][j] + bs[col];
        }
    }
}

// ---------------------------------------------------------------------------
// Kernel 2: fused position-encoding + attention-logit MLP + softmax + scatter
// block = 128 threads = 4 warps. Each warp handles 2 points:
//   lane = 16*half + j,  half -> point,  j -> neighbor (NS=16).
// Each lane owns one neighbor end-to-end in registers; all weights broadcast
// from smem. Cross-lane work: softmax shuffles (16-wide) + smem output sum.
// ---------------------------------------------------------------------------
__global__ __launch_bounds__(128) void attn_kernel(
    const float* __restrict__ p,
    const int*   __restrict__ nidx,
    const float* __restrict__ p1_W, const float* __restrict__ p1_b,
    const float* __restrict__ p_g,  const float* __restrict__ p_bb,
    const float* __restrict__ p2_W, const float* __restrict__ p2_b,
    const float* __restrict__ w_g1, const float* __restrict__ w_b1,
    const float* __restrict__ w1_W, const float* __restrict__ w1_b,
    const float* __restrict__ w_g2, const float* __restrict__ w_b2,
    const float* __restrict__ w2_W, const float* __restrict__ w2_b,
    float* __restrict__ out)
{
    __shared__ __align__(16) float P2s[3][64];     // p2_W rows
    __shared__ __align__(16) float P2bs[64];
    __shared__ __align__(16) float ws1s[64], wb1s[64];
    __shared__ __align__(16) float W1s[64][8];     // w1_W  [c][k]
    __shared__ __align__(16) float W2s[64];        // w2_W  [m*8+k]
    __shared__ float p1Ws[9], p1bs[3], pscs[3], pbbs[3];
    __shared__ float ws2s[8], wb2s[8], w2bs[8], w1bs[8];
    __shared__ __align__(16) float S[8][16][68];   // gv+pe per (slot, j, c)
    __shared__ __align__(16) float Wt[8][16][8];   // softmax weights

    const float RS = rsqrtf(1.0f + 1e-5f);
    const int tid = threadIdx.x;

    const int warp = tid >> 5, lane = tid & 31;
    const int half = lane >> 4, j = lane & 15;
    const int slot = warp * 2 + half;              // 0..7 point slot in block
    const int n    = blockIdx.x * 8 + slot;

    // issue index + coordinate gathers before anything else (front-batch LDGs)
    const int nb = nidx[n * NS + j];
    const float nbx = __ldg(&p[nb * 3 + 0]);
    const float nby = __ldg(&p[nb * 3 + 1]);
    const float nbz = __ldg(&p[nb * 3 + 2]);
    const float cpx = __ldg(&p[n * 3 + 0]);
    const float cpy = __ldg(&p[n * 3 + 1]);
    const float cpz = __ldg(&p[n * 3 + 2]);

    if (tid < 64) {
        P2bs[tid] = p2_b[tid];
        ws1s[tid] = w_g1[tid] * RS;
        wb1s[tid] = w_b1[tid];
        W2s[tid]  = w2_W[tid];
        #pragma unroll
        for (int d = 0; d < 3; d++) P2s[d][tid] = p2_W[d * 64 + tid];
        #pragma unroll
        for (int k = 0; k < 8; k++) W1s[tid][k] = w1_W[tid * 8 + k];
    }
    if (tid < 9) p1Ws[tid] = p1_W[tid];
    if (tid < 3) { p1bs[tid] = p1_b[tid]; pscs[tid] = p_g[tid] * RS; pbbs[tid] = p_bb[tid]; }
    if (tid < 8) { ws2s[tid] = w_g2[tid] * RS; wb2s[tid] = w_b2[tid];
                   w2bs[tid] = w2_b[tid];      w1bs[tid] = w1_b[tid]; }
    __syncthreads();

    // relative position -> linear_p first stage (3->3, BN, ReLU)
    const float prx = nbx - cpx;
    const float pry = nby - cpy;
    const float prz = nbz - cpz;
    float u0, u1, u2;
    {
        float v0 = fmaf(prx, p1Ws[0], fmaf(pry, p1Ws[3], fmaf(prz, p1Ws[6], p1bs[0])));
        float v1 = fmaf(prx, p1Ws[1], fmaf(pry, p1Ws[4], fmaf(prz, p1Ws[7], p1bs[1])));
        float v2 = fmaf(prx, p1Ws[2], fmaf(pry, p1Ws[5], fmaf(prz, p1Ws[8], p1bs[2])));
        u0 = fmaxf(fmaf(v0, pscs[0], pbbs[0]), 0.f);
        u1 = fmaxf(fmaf(v1, pscs[1], pbbs[1]), 0.f);
        u2 = fmaxf(fmaf(v2, pscs[2], pbbs[2]), 0.f);
    }

    const float4* gk4p = (const float4*)(g_qkv + 1 * (N_PTS * C) + nb * C);
    const float4* gv4p = (const float4*)(g_qkv + 2 * (N_PTS * C) + nb * C);
    const float4* xq4p = (const float4*)(g_qkv + n * C);

    float h[8];
    #pragma unroll
    for (int k = 0; k < 8; k++) h[k] = w1bs[k];

    #pragma unroll
    for (int it = 0; it < 16; it++) {
        const float4 gk = __ldg(&gk4p[it]);
        const float4 gv = __ldg(&gv4p[it]);
        const float4 q4 = __ldg(&xq4p[it]);
        const float4 pb4 = *(const float4*)&P2bs[it * 4];
        const float4 a0  = *(const float4*)&P2s[0][it * 4];
        const float4 a1  = *(const float4*)&P2s[1][it * 4];
        const float4 a2  = *(const float4*)&P2s[2][it * 4];
        const float4 s1  = *(const float4*)&ws1s[it * 4];
        const float4 b1  = *(const float4*)&wb1s[it * 4];

        float pe[4], aa[4];
        pe[0] = fmaf(u0, a0.x, fmaf(u1, a1.x, fmaf(u2, a2.x, pb4.x)));
        pe[1] = fmaf(u0, a0.y, fmaf(u1, a1.y, fmaf(u2, a2.y, pb4.y)));
        pe[2] = fmaf(u0, a0.z, fmaf(u1, a1.z, fmaf(u2, a2.z, pb4.z)));
        pe[3] = fmaf(u0, a0.w, fmaf(u1, a1.w, fmaf(u2, a2.w, pb4.w)));
        aa[0] = fmaxf(fmaf(gk.x - q4.x + pe[0], s1.x, b1.x), 0.f);
        aa[1] = fmaxf(fmaf(gk.y - q4.y + pe[1], s1.y, b1.y), 0.f);
        aa[2] = fmaxf(fmaf(gk.z - q4.z + pe[2], s1.z, b1.z), 0.f);
        aa[3] = fmaxf(fmaf(gk.w - q4.w + pe[3], s1.w, b1.w), 0.f);

        const float4* wr = (const float4*)&W1s[it * 4][0];  // 2 float4 per row
        #pragma unroll
        for (int m = 0; m < 4; m++) {
            const float am = aa[m];
            const float4 wlo = wr[2 * m], whi = wr[2 * m + 1];
            h[0] = fmaf(am, wlo.x, h[0]); h[1] = fmaf(am, wlo.y, h[1]);
            h[2] = fmaf(am, wlo.z, h[2]); h[3] = fmaf(am, wlo.w, h[3]);
            h[4] = fmaf(am, whi.x, h[4]); h[5] = fmaf(am, whi.y, h[5]);
            h[6] = fmaf(am, whi.z, h[6]); h[7] = fmaf(am, whi.w, h[7]);
        }
        float4 ge;
        ge.x = gv.x + pe[0]; ge.y = gv.y + pe[1];
        ge.z = gv.z + pe[2]; ge.w = gv.w + pe[3];
        *(float4*)&S[slot][j][it * 4] = ge;
    }

    // second MLP layer (8->8) + softmax over neighbors (16 lanes per half)
    float b2[8];
    #pragma unroll
    for (int k = 0; k < 8; k++)
        b2[k] = fmaxf(fmaf(h[k], ws2s[k], wb2s[k]), 0.f);

    #pragma unroll
    for (int k = 0; k < 8; k++) {
        float lg = w2bs[k];
        #pragma unroll
        for (int m = 0; m < 8; m++) lg = fmaf(b2[m], W2s[m * 8 + k], lg);
        float mx = lg;
        mx = fmaxf(mx, __shfl_xor_sync(0xffffffffu, mx, 1));
        mx = fmaxf(mx, __shfl_xor_sync(0xffffffffu, mx, 2));
        mx = fmaxf(mx, __shfl_xor_sync(0xffffffffu, mx, 4));
        mx = fmaxf(mx, __shfl_xor_sync(0xffffffffu, mx, 8));
        float e = __expf(lg - mx);
        float s = e;
        s += __shfl_xor_sync(0xffffffffu, s, 1);
        s += __shfl_xor_sync(0xffffffffu, s, 2);
        s += __shfl_xor_sync(0xffffffffu, s, 4);
        s += __shfl_xor_sync(0xffffffffu, s, 8);
        Wt[slot][j][k] = e / s;
    }
    __syncwarp();

    // output: lane now covers channels [j*4 .. j*4+3] of its point (same slot)
    const int cs = (j * 4) & 7;                   // 0 or 4, float4-aligned
    float4 acc4 = make_float4(0.f, 0.f, 0.f, 0.f);
    #pragma unroll
    for (int jj = 0; jj < 16; jj++) {
        const float4 ge = *(const float4*)&S[slot][jj][j * 4];
        const float4 w4 = *(const float4*)&Wt[slot][jj][cs];
        acc4.x = fmaf(w4.x, ge.x, acc4.x);
        acc4.y = fmaf(w4.y, ge.y, acc4.y);
        acc4.z = fmaf(w4.z, ge.z, acc4.z);
        acc4.w = fmaf(w4.w, ge.w, acc4.w);
    }
    *(float4*)&out[n * C + j * 4] = acc4;
}

// ---------------------------------------------------------------------------
extern "C" void kernel_launch(void* const* d_in, const int* in_sizes, int n_in,
                              void* d_out, int out_size)
{
    const float* p   = (const float*)d_in[0];
    const float* x   = (const float*)d_in[1];
    const int*   ni  = (const int*)  d_in[2];
    const float* Wq  = (const float*)d_in[3];
    const float* bq  = (const float*)d_in[4];
    const float* Wk  = (const float*)d_in[5];
    const float* bk  = (const float*)d_in[6];
    const float* Wv  = (const float*)d_in[7];
    const float* bv  = (const float*)d_in[8];
    const float* p1W = (const float*)d_in[9];
    const float* p1b = (const float*)d_in[10];
    const float* pg  = (const float*)d_in[11];
    const float* pb  = (const float*)d_in[12];
    const float* p2W = (const float*)d_in[13];
    const float* p2b = (const float*)d_in[14];
    const float* wg1 = (const float*)d_in[15];
    const float* wb1 = (const float*)d_in[16];
    const float* w1W = (const float*)d_in[17];
    const float* w1b = (const float*)d_in[18];
    const float* wg2 = (const float*)d_in[19];
    const float* wb2 = (const float*)d_in[20];
    const float* w2W = (const float*)d_in[21];
    const float* w2b = (const float*)d_in[22];
    float* out = (float*)d_out;

    proj_kernel<<<N_PTS / 64, 256>>>(x, Wq, bq, Wk, bk, Wv, bv);
    attn_kernel<<<N_PTS / 8, 128>>>(p, ni, p1W, p1b, pg, pb, p2W, p2b,
                                    wg1, wb1, w1W, w1b, wg2, wb2, w2W, w2b, out);
}

// round 15
// speedup vs baseline: 1.1335x; 1.1335x over previous
#include <cuda_runtime.h>

#define N_PTS 65536
#define C 64
#define NS 16

// scratch for xq | xk | xv  (3 * 16MB)
__device__ __align__(256) float g_qkv[3 * N_PTS * C];

// ---------------------------------------------------------------------------
// Kernel 1: fused q/k/v projection GEMM  (65536x64) @ (64x192)  (unchanged)
// ---------------------------------------------------------------------------
__global__ __launch_bounds__(256) void proj_kernel(
    const float* __restrict__ x,
    const float* __restrict__ Wq, const float* __restrict__ bq,
    const float* __restrict__ Wk, const float* __restrict__ bk,
    const float* __restrict__ Wv, const float* __restrict__ bv)
{
    __shared__ float Ws[32][192];
    __shared__ float Xs[64][36];
    __shared__ float bs[192];

    const int tid = threadIdx.x;
    const int pB  = blockIdx.x * 64;

    if (tid < 192)
        bs[tid] = (tid < 64) ? bq[tid] : (tid < 128 ? bk[tid - 64] : bv[tid - 128]);

    const int pg = tid >> 4;
    const int og = tid & 15;

    float acc[4][12];
    #pragma unroll
    for (int i = 0; i < 4; i++)
        #pragma unroll
        for (int j = 0; j < 12; j++) acc[i][j] = 0.f;

    for (int kt = 0; kt < 2; kt++) {
        __syncthreads();
        for (int idx = tid; idx < 32 * 192; idx += 256) {
            int kk = idx / 192, col = idx % 192;
            int mat = col >> 6, ch = col & 63;
            const float* Wp = (mat == 0) ? Wq : ((mat == 1) ? Wk : Wv);
            Ws[kk][col] = Wp[(kt * 32 + kk) * 64 + ch];
        }
        for (int idx = tid; idx < 64 * 32; idx += 256) {
            int pt = idx >> 5, kk = idx & 31;
            Xs[pt][kk] = x[(pB + pt) * 64 + kt * 32 + kk];
        }
        __syncthreads();

        #pragma unroll 8
        for (int kk = 0; kk < 32; kk++) {
            float xp[4], wv[12];
            #pragma unroll
            for (int i = 0; i < 4; i++) xp[i] = Xs[pg * 4 + i][kk];
            #pragma unroll
            for (int j = 0; j < 12; j++) wv[j] = Ws[kk][og * 12 + j];
            #pragma unroll
            for (int i = 0; i < 4; i++)
                #pragma unroll
                for (int j = 0; j < 12; j++)
                    acc[i][j] = fmaf(xp[i], wv[j], acc[i][j]);
        }
    }

    #pragma unroll
    for (int i = 0; i < 4; i++) {
        int pt = pB + pg * 4 + i;
        #pragma unroll
        for (int j = 0; j < 12; j++) {
            int col = og * 12 + j;
            int mat = col >> 6, ch = col & 63;
            g_qkv[mat * (N_PTS * C) + pt * C + ch] = acc[i][j] + bs[col];
        }
    }
}

// ---------------------------------------------------------------------------
// Kernel 2 v2: smem-staged gathers.
// block = 128 threads = 4 warps = 8 points. One half-warp per point,
// lane = neighbor. K (then V) rows are gathered COALESCED into buf by the
// whole block (2 L1 wavefronts/row instead of ~32), compute reads smem.
// Softmax weights stay in registers and are folded into the pass-B store.
// ---------------------------------------------------------------------------
__global__ __launch_bounds__(128) void attn_kernel(
    const float* __restrict__ p,
    const int*   __restrict__ nidx,
    const float* __restrict__ p1_W, const float* __restrict__ p1_b,
    const float* __restrict__ p_g,  const float* __restrict__ p_bb,
    const float* __restrict__ p2_W, const float* __restrict__ p2_b,
    const float* __restrict__ w_g1, const float* __restrict__ w_b1,
    const float* __restrict__ w1_W, const float* __restrict__ w1_b,
    const float* __restrict__ w_g2, const float* __restrict__ w_b2,
    const float* __restrict__ w2_W, const float* __restrict__ w2_b,
    float* __restrict__ out)
{
    __shared__ __align__(16) float buf[128][68];   // K rows, then V rows, then ge (34.8KB)
    __shared__ __align__(16) float Qs[8][68];      // q rows of the 8 points
    __shared__ __align__(16) float P2s[3][64];
    __shared__ __align__(16) float P2bs[64];
    __shared__ __align__(16) float ws1s[64], wb1s[64];
    __shared__ __align__(16) float W1s[64][8];
    __shared__ __align__(16) float W2s[64];
    __shared__ float p1Ws[9], p1bs[3], pscs[3], pbbs[3];
    __shared__ float ws2s[8], wb2s[8], w2bs[8], w1bs[8];
    __shared__ int   nbs[128];

    const float RS = rsqrtf(1.0f + 1e-5f);
    const int tid  = threadIdx.x;
    const int warp = tid >> 5, lane = tid & 31;
    const int half = lane >> 4, j = lane & 15;
    const int slot = warp * 2 + half;              // 0..7
    const int n    = blockIdx.x * 8 + slot;

    // stage neighbor ids (contiguous slice), q rows, and all weights
    nbs[tid] = nidx[blockIdx.x * 128 + tid];
    {
        int qr = tid >> 4, qc = (tid & 15) * 4;
        *(float4*)&Qs[qr][qc] =
            *(const float4*)(g_qkv + (blockIdx.x * 8 + qr) * C + qc);
    }
    if (tid < 64) {
        P2bs[tid] = p2_b[tid];
        ws1s[tid] = w_g1[tid] * RS;
        wb1s[tid] = w_b1[tid];
        W2s[tid]  = w2_W[tid];
        #pragma unroll
        for (int d = 0; d < 3; d++) P2s[d][tid] = p2_W[d * 64 + tid];
        #pragma unroll
        for (int k = 0; k < 8; k++) W1s[tid][k] = w1_W[tid * 8 + k];
    }
    if (tid < 9) p1Ws[tid] = p1_W[tid];
    if (tid < 3) { p1bs[tid] = p1_b[tid]; pscs[tid] = p_g[tid] * RS; pbbs[tid] = p_bb[tid]; }
    if (tid < 8) { ws2s[tid] = w_g2[tid] * RS; wb2s[tid] = w_b2[tid];
                   w2bs[tid] = w2_b[tid];      w1bs[tid] = w1_b[tid]; }
    __syncthreads();

    // per-lane relative position -> u (linear_p stage 1)
    const int nb = nbs[slot * 16 + j];
    const float prx = __ldg(&p[nb * 3 + 0]) - __ldg(&p[n * 3 + 0]);
    const float pry = __ldg(&p[nb * 3 + 1]) - __ldg(&p[n * 3 + 1]);
    const float prz = __ldg(&p[nb * 3 + 2]) - __ldg(&p[n * 3 + 2]);
    float u0, u1, u2;
    {
        float v0 = fmaf(prx, p1Ws[0], fmaf(pry, p1Ws[3], fmaf(prz, p1Ws[6], p1bs[0])));
        float v1 = fmaf(prx, p1Ws[1], fmaf(pry, p1Ws[4], fmaf(prz, p1Ws[7], p1bs[1])));
        float v2 = fmaf(prx, p1Ws[2], fmaf(pry, p1Ws[5], fmaf(prz, p1Ws[8], p1bs[2])));
        u0 = fmaxf(fmaf(v0, pscs[0], pbbs[0]), 0.f);
        u1 = fmaxf(fmaf(v1, pscs[1], pbbs[1]), 0.f);
        u2 = fmaxf(fmaf(v2, pscs[2], pbbs[2]), 0.f);
    }

    // ---- coalesced gather of the 128 K rows ----
    const float* Ksrc = g_qkv + 1 * (N_PTS * C);
    #pragma unroll 4
    for (int i = 0; i < 16; i++) {
        int idx = tid + i * 128;
        int r = idx >> 4, c4 = (idx & 15) * 4;
        *(float4*)&buf[r][c4] = *(const float4*)(Ksrc + nbs[r] * C + c4);
    }
    __syncthreads();

    // ---- pass A: logits MLP layer 1 (lane-per-neighbor, reads smem) ----
    const int myrow = slot * 16 + j;
    float h[8];
    #pragma unroll
    for (int k = 0; k < 8; k++) h[k] = w1bs[k];

    #pragma unroll
    for (int it = 0; it < 16; it++) {
        const float4 k4  = *(const float4*)&buf[myrow][it * 4];
        const float4 q4  = *(const float4*)&Qs[slot][it * 4];
        const float4 pb4 = *(const float4*)&P2bs[it * 4];
        const float4 a0  = *(const float4*)&P2s[0][it * 4];
        const float4 a1  = *(const float4*)&P2s[1][it * 4];
        const float4 a2  = *(const float4*)&P2s[2][it * 4];
        const float4 s1  = *(const float4*)&ws1s[it * 4];
        const float4 b1  = *(const float4*)&wb1s[it * 4];

        float pe0 = fmaf(u0, a0.x, fmaf(u1, a1.x, fmaf(u2, a2.x, pb4.x)));
        float pe1 = fmaf(u0, a0.y, fmaf(u1, a1.y, fmaf(u2, a2.y, pb4.y)));
        float pe2 = fmaf(u0, a0.z, fmaf(u1, a1.z, fmaf(u2, a2.z, pb4.z)));
        float pe3 = fmaf(u0, a0.w, fmaf(u1, a1.w, fmaf(u2, a2.w, pb4.w)));
        float aa[4];
        aa[0] = fmaxf(fmaf(k4.x - q4.x + pe0, s1.x, b1.x), 0.f);
        aa[1] = fmaxf(fmaf(k4.y - q4.y + pe1, s1.y, b1.y), 0.f);
        aa[2] = fmaxf(fmaf(k4.z - q4.z + pe2, s1.z, b1.z), 0.f);
        aa[3] = fmaxf(fmaf(k4.w - q4.w + pe3, s1.w, b1.w), 0.f);

        const float4* wr = (const float4*)&W1s[it * 4][0];
        #pragma unroll
        for (int m = 0; m < 4; m++) {
            const float am = aa[m];
            const float4 wlo = wr[2 * m], whi = wr[2 * m + 1];
            h[0] = fmaf(am, wlo.x, h[0]); h[1] = fmaf(am, wlo.y, h[1]);
            h[2] = fmaf(am, wlo.z, h[2]); h[3] = fmaf(am, wlo.w, h[3]);
            h[4] = fmaf(am, whi.x, h[4]); h[5] = fmaf(am, whi.y, h[5]);
            h[6] = fmaf(am, whi.z, h[6]); h[7] = fmaf(am, whi.w, h[7]);
        }
    }
    __syncthreads();   // all K reads done before V overwrites buf

    // ---- coalesced gather of the 128 V rows (reuses buf) ----
    const float* Vsrc = g_qkv + 2 * (N_PTS * C);
    #pragma unroll 4
    for (int i = 0; i < 16; i++) {
        int idx = tid + i * 128;
        int r = idx >> 4, c4 = (idx & 15) * 4;
        *(float4*)&buf[r][c4] = *(const float4*)(Vsrc + nbs[r] * C + c4);
    }

    // ---- MLP layer 2 + softmax over neighbors (registers + shuffles) ----
    float b2[8];
    #pragma unroll
    for (int k = 0; k < 8; k++)
        b2[k] = fmaxf(fmaf(h[k], ws2s[k], wb2s[k]), 0.f);

    float wt[8];
    #pragma unroll
    for (int k = 0; k < 8; k++) {
        float lg = w2bs[k];
        #pragma unroll
        for (int m = 0; m < 8; m++) lg = fmaf(b2[m], W2s[m * 8 + k], lg);
        float mx = lg;
        mx = fmaxf(mx, __shfl_xor_sync(0xffffffffu, mx, 1));
        mx = fmaxf(mx, __shfl_xor_sync(0xffffffffu, mx, 2));
        mx = fmaxf(mx, __shfl_xor_sync(0xffffffffu, mx, 4));
        mx = fmaxf(mx, __shfl_xor_sync(0xffffffffu, mx, 8));
        float e = __expf(lg - mx);
        float s = e;
        s += __shfl_xor_sync(0xffffffffu, s, 1);
        s += __shfl_xor_sync(0xffffffffu, s, 2);
        s += __shfl_xor_sync(0xffffffffu, s, 4);
        s += __shfl_xor_sync(0xffffffffu, s, 8);
        wt[k] = e / s;
    }
    __syncthreads();   // V gather complete

    // ---- pass B: ge = (v + pe) * wt, stored in place ----
    #pragma unroll
    for (int it = 0; it < 16; it++) {
        const float4 v4  = *(const float4*)&buf[myrow][it * 4];
        const float4 pb4 = *(const float4*)&P2bs[it * 4];
        const float4 a0  = *(const float4*)&P2s[0][it * 4];
        const float4 a1  = *(const float4*)&P2s[1][it * 4];
        const float4 a2  = *(const float4*)&P2s[2][it * 4];
        float pe0 = fmaf(u0, a0.x, fmaf(u1, a1.x, fmaf(u2, a2.x, pb4.x)));
        float pe1 = fmaf(u0, a0.y, fmaf(u1, a1.y, fmaf(u2, a2.y, pb4.y)));
        float pe2 = fmaf(u0, a0.z, fmaf(u1, a1.z, fmaf(u2, a2.z, pb4.z)));
        float pe3 = fmaf(u0, a0.w, fmaf(u1, a1.w, fmaf(u2, a2.w, pb4.w)));
        const int kb = (it & 1) * 4;   // channel c -> weight index c & 7
        float4 ge;
        ge.x = (v4.x + pe0) * wt[kb + 0];
        ge.y = (v4.y + pe1) * wt[kb + 1];
        ge.z = (v4.z + pe2) * wt[kb + 2];
        ge.w = (v4.w + pe3) * wt[kb + 3];
        *(float4*)&buf[myrow][it * 4] = ge;
    }
    __syncwarp();      // rows of a slot are produced & consumed by the same warp

    // ---- epilogue: out[n][c] = sum_j ge[j][c] ----
    float4 acc4 = make_float4(0.f, 0.f, 0.f, 0.f);
    #pragma unroll
    for (int jj = 0; jj < 16; jj++) {
        const float4 s4 = *(const float4*)&buf[slot * 16 + jj][j * 4];
        acc4.x += s4.x; acc4.y += s4.y; acc4.z += s4.z; acc4.w += s4.w;
    }
    *(float4*)&out[n * C + j * 4] = acc4;
}

// ---------------------------------------------------------------------------
extern "C" void kernel_launch(void* const* d_in, const int* in_sizes, int n_in,
                              void* d_out, int out_size)
{
    const float* p   = (const float*)d_in[0];
    const float* x   = (const float*)d_in[1];
    const int*   ni  = (const int*)  d_in[2];
    const float* Wq  = (const float*)d_in[3];
    const float* bq  = (const float*)d_in[4];
    const float* Wk  = (const float*)d_in[5];
    const float* bk  = (const float*)d_in[6];
    const float* Wv  = (const float*)d_in[7];
    const float* bv  = (const float*)d_in[8];
    const float* p1W = (const float*)d_in[9];
    const float* p1b = (const float*)d_in[10];
    const float* pg  = (const float*)d_in[11];
    const float* pb  = (const float*)d_in[12];
    const float* p2W = (const float*)d_in[13];
    const float* p2b = (const float*)d_in[14];
    const float* wg1 = (const float*)d_in[15];
    const float* wb1 = (const float*)d_in[16];
    const float* w1W = (const float*)d_in[17];
    const float* w1b = (const float*)d_in[18];
    const float* wg2 = (const float*)d_in[19];
    const float* wb2 = (const float*)d_in[20];
    const float* w2W = (const float*)d_in[21];
    const float* w2b = (const float*)d_in[22];
    float* out = (float*)d_out;

    proj_kernel<<<N_PTS / 64, 256>>>(x, Wq, bq, Wk, bk, Wv, bv);
    attn_kernel<<<N_PTS / 8, 128>>>(p, ni, p1W, p1b, pg, pb, p2W, p2b,
                                    wg1, wb1, w1W, w1b, wg2, wb2, w2W, w2b, out);
}